// round 8
// baseline (speedup 1.0000x reference)
#include <cuda_runtime.h>

typedef unsigned long long u64;

// ---------------- problem constants ----------------
#define CC 8
#define KK 1024
#define NT 16
#define TILES 256              // 4096 / NT
#define THREADS 1024
#define NBLOCKS 148            // one block per SM, contiguous task ranges

// ---------------- smem layout (float offsets) ----------------
#define OFF_CB   0             // 32768: 1024 rows x 128B, SW128-swizzled
#define OFF_DS   32768         // 16384: [16 n][1024 k]  dists -> q (col-swizzled)
#define OFF_ZFT  49152         // 1024:  2 x [32 j][16 n]
#define OFF_ZFTT 50176         // 1056:  2 x [16 n][stride 33 j]  (transposed)
#define OFF_RED  51232         // 4096:  [8 slab][16 n][32 j]
#define OFF_SRM  55328         // 32 per-warp rmin
#define OFF_SRK  55360         // 32 per-warp kmin (int)
#define OFF_SRZ  55392         // 32 per-warp Z
#define OFF_SRS  55424         // 32 per-warp sed
#define OFF_IDX  55456         // 16 idx + flag
#define SMEM_FLOATS 55480
#define SMEM_BYTES (SMEM_FLOATS * 4)   // 221920 B

// ---------------- output packing (float32, tuple order) ----------------
#define O_IDX   1048576u
#define O_Q     1081344u
#define O_SC    34635776u

// ---------------- global scratch ----------------
__device__ float g_qbar[CC * KK];
__device__ float g_comm;
__device__ float g_ne;
__device__ float g_qd;
__device__ unsigned int g_count;

// ---------------- f32x2 helpers ----------------
__device__ __forceinline__ void fma2(u64 &d, u64 a, u64 b) {
    asm("fma.rn.f32x2 %0, %1, %2, %0;" : "+l"(d) : "l"(a), "l"(b));
}
__device__ __forceinline__ u64 add2(u64 a, u64 b) {
    u64 r; asm("add.rn.f32x2 %0, %1, %2;" : "=l"(r) : "l"(a), "l"(b)); return r;
}
__device__ __forceinline__ u64 dup2(float x) {
    u64 r; asm("mov.b64 %0, {%1, %1};" : "=l"(r) : "f"(x)); return r;
}
__device__ __forceinline__ void unpk2(u64 v, float &lo, float &hi) {
    asm("mov.b64 {%0, %1}, %2;" : "=f"(lo), "=f"(hi) : "l"(v));
}
__device__ __forceinline__ u64 shfl_xor64(u64 v, int m) {
    return __shfl_xor_sync(0xffffffffu, v, m);
}

// ---------------- swizzled codebook addressing (128B rows, SW128) ----------
__device__ __forceinline__ const float4* cb_vec(const char* cbb, int k, int j4) {
    return (const float4*)(cbb + k * 128 + ((j4 * 16) ^ ((k & 7) << 4)));
}
__device__ __forceinline__ float cb_el(const char* cbb, int k, int j) {
    return *(const float*)(cbb + k * 128 + ((j * 4) ^ ((k & 7) << 4)));
}

// ds column swizzle (float index involution): xor bits[3:2] with bits[6:5]
__device__ __forceinline__ int dsx(int i) { return i ^ ((i >> 3) & 12); }

__global__ void __launch_bounds__(THREADS, 1)
lgq_main(const float* __restrict__ z, const float* __restrict__ cbg,
         float* __restrict__ out)
{
    extern __shared__ float sm[];
    char*  cbb  = (char*)sm;
    float* ds   = sm + OFF_DS;
    float* zft  = sm + OFF_ZFT;
    float* zftT = sm + OFF_ZFTT;
    float* red  = sm + OFF_RED;
    float* srm  = sm + OFF_SRM;
    int*   srk  = (int*)(sm + OFF_SRK);
    float* srz  = sm + OFF_SRZ;
    float* srs  = sm + OFF_SRS;
    int*   idxs = (int*)(sm + OFF_IDX);

    const int t    = threadIdx.x;
    const int w    = t >> 5;
    const int lane = t & 31;
    const int bx   = blockIdx.x;
    const int jj   = (t & 511) >> 4;   // staging j (0..31), t<512 only
    const int ni   = t & 15;           // staging n-within-tile

    // phase-1 mapping
    const int k0  = t & 511;           // k column (and k0+512)
    const int h1  = t >> 9;            // n-half (0/1)
    const int kx0 = dsx(k0);           // swizzled; dsx(k0+512)=kx0+512
    // phase-2 mapping
    const int n2p = w & 15;            // row n
    const int hh  = w >> 4;            // k-half
    const int lx  = lane ^ ((lane >> 3) & 3);
    // phase-3 mapping
    const int s3  = w & 7;             // k slab (128 k)
    const int nq  = w >> 3;            // n quad (4 n)
    const int ks  = lane >> 3;         // k sub-chunk (32 k)
    const int jg  = lane & 7;          // j group of 4

    // ---- contiguous task range: task = (c << 8) | tile ----
    const int start = bx * 13 + min(bx, 124);
    const int gend  = start + 13 + (bx < 124 ? 1 : 0);
    int c = start >> 8;

    float zsq_acc = 0.0f;

    // ---- stage codebook c (swizzled) + zf of first tile ----
    {
        const float4* cb4 = (const float4*)(cbg + (size_t)c * (KK * 32));
        #pragma unroll
        for (int it = 0; it < 8; it++) {
            int i = t + it * THREADS;
            float4 v = cb4[i];
            int k = i >> 3, j4 = i & 7;
            *(float4*)(cbb + k * 128 + ((j4 * 16) ^ ((k & 7) << 4))) = v;
        }
        if (t < 512) {
            int n = (start & 255) * NT + ni;
            int b = n >> 10;
            float v = z[(size_t)(b * 256 + c * 32 + jj) * 1024 + (n & 1023)];
            zft[jj * 16 + ni]  = v;
            zftT[ni * 33 + jj] = v;
            zsq_acc += v * v;
        }
    }
    __syncthreads();

    // ---- codeword norms for k0, k0+512 ----
    float cq[2];
    #pragma unroll
    for (int m = 0; m < 2; m++) {
        int k = k0 + 512 * m;
        float s = 0.0f;
        #pragma unroll
        for (int j4 = 0; j4 < 8; j4++) {
            float4 v = *cb_vec(cbb, k, j4);
            s += v.x * v.x + v.y * v.y + v.z * v.z + v.w * v.w;
        }
        cq[m] = s;
    }

    float ct_comm = 0.0f;
    float acc_ne = 0.0f, acc_qd = 0.0f;
    float qbr = 0.0f;                  // qbar partial for k = t
    int buf = 0;

    for (int gi = start; gi < gend; gi++) {
        const int nb = (gi & 255) * NT;

        // ---- prefetch next task's zf ----
        const int gn = gi + 1;
        const bool has_next = (gn < gend);
        const int nc = gn >> 8;
        float zn = 0.0f;
        if (has_next && t < 512) {
            int n = (gn & 255) * NT + ni;
            int b = n >> 10;
            zn = z[(size_t)(b * 256 + nc * 32 + jj) * 1024 + (n & 1023)];
        }

        // ====== phase 1: r = cbsq - 2*cross, thread = (k0, n-half) ========
        {
            u64 acc[4][2];
            #pragma unroll
            for (int np = 0; np < 4; np++) { acc[np][0] = 0ull; acc[np][1] = 0ull; }

            const int sx = (k0 & 7) << 4;
            const float* zb = zft + buf * 512 + h1 * 8;

            #pragma unroll
            for (int j4 = 0; j4 < 8; j4++) {
                const int off = (j4 * 16) ^ sx;
                float4 cv0 = *(const float4*)(cbb + k0 * 128 + off);
                float4 cv1 = *(const float4*)(cbb + (k0 + 512) * 128 + off);
                #pragma unroll
                for (int e = 0; e < 4; e++) {
                    int j = j4 * 4 + e;
                    const ulonglong2* zp = (const ulonglong2*)(zb + j * 16);
                    ulonglong2 zA = zp[0];      // n pairs 0,1 of this half
                    float e0 = (e == 0) ? cv0.x : (e == 1) ? cv0.y
                             : (e == 2) ? cv0.z : cv0.w;
                    float e1 = (e == 0) ? cv1.x : (e == 1) ? cv1.y
                             : (e == 2) ? cv1.z : cv1.w;
                    u64 d0 = dup2(e0), d1 = dup2(e1);
                    fma2(acc[0][0], zA.x, d0); fma2(acc[0][1], zA.x, d1);
                    fma2(acc[1][0], zA.y, d0); fma2(acc[1][1], zA.y, d1);
                    ulonglong2 zB = zp[1];      // n pairs 2,3
                    fma2(acc[2][0], zB.x, d0); fma2(acc[2][1], zB.x, d1);
                    fma2(acc[3][0], zB.y, d0); fma2(acc[3][1], zB.y, d1);
                }
            }
            #pragma unroll
            for (int np = 0; np < 4; np++)
                #pragma unroll
                for (int m = 0; m < 2; m++) {
                    float a, b2; unpk2(acc[np][m], a, b2);
                    int kx = kx0 + 512 * m;
                    int n0 = h1 * 8 + 2 * np;
                    ds[n0 * 1024 + kx]       = fmaf(-2.0f, a,  cq[m]);
                    ds[(n0 + 1) * 1024 + kx] = fmaf(-2.0f, b2, cq[m]);
                }
        }
        __syncthreads();

        // ====== phase 2: softmax/argmin, 2 warps per row (k-halves) =======
        {
            float* row = ds + n2p * 1024;
            const float4* row4  = (const float4*)row;
            float4*       row4w = (float4*)row;
            float dv[16];
            #pragma unroll
            for (int m4 = 0; m4 < 4; m4++) {
                float4 v = row4[hh * 128 + lx + 32 * m4];
                dv[m4 * 4 + 0] = v.x; dv[m4 * 4 + 1] = v.y;
                dv[m4 * 4 + 2] = v.z; dv[m4 * 4 + 3] = v.w;
            }
            float rmin = 3.4e38f; int kmin = 1 << 30;
            #pragma unroll
            for (int i = 0; i < 16; i++) {
                int k = hh * 512 + 4 * lane + 128 * (i >> 2) + (i & 3);
                float dd = dv[i];
                if (dd < rmin || (dd == rmin && k < kmin)) { rmin = dd; kmin = k; }
            }
            #pragma unroll
            for (int off = 16; off; off >>= 1) {
                float od = __shfl_xor_sync(0xffffffffu, rmin, off);
                int   ok = __shfl_xor_sync(0xffffffffu, kmin, off);
                if (od < rmin || (od == rmin && ok < kmin)) { rmin = od; kmin = ok; }
            }
            if (lane == 0) { srm[w] = rmin; srk[w] = kmin; }
            __syncthreads();
            {
                float om = srm[w ^ 16]; int ok = srk[w ^ 16];
                if (om < rmin || (om == rmin && ok < kmin)) { rmin = om; kmin = ok; }
            }
            float Z = 0.0f, sed = 0.0f;
            #pragma unroll
            for (int i = 0; i < 16; i++) {
                float told = dv[i];
                float ev = __expf((rmin - told) * 0.5f);
                Z += ev;
                sed = fmaf(ev, told, sed);
                dv[i] = ev;
            }
            #pragma unroll
            for (int off = 16; off; off >>= 1) {
                Z   += __shfl_xor_sync(0xffffffffu, Z, off);
                sed += __shfl_xor_sync(0xffffffffu, sed, off);
            }
            if (lane == 0) { srz[w] = Z; srs[w] = sed; }
            __syncthreads();
            float Zt   = Z   + srz[w ^ 16];
            float sedt = sed + srs[w ^ 16];
            float rZ = __fdividef(1.0f, Zt);
            float qd = sedt * rZ;

            int n = nb + n2p;
            float4* gq4 = (float4*)(out + O_Q + ((size_t)n * 8 + c) * 1024);
            #pragma unroll
            for (int m4 = 0; m4 < 4; m4++) {
                float4 qv;
                qv.x = dv[m4 * 4 + 0] * rZ; qv.y = dv[m4 * 4 + 1] * rZ;
                qv.z = dv[m4 * 4 + 2] * rZ; qv.w = dv[m4 * 4 + 3] * rZ;
                row4w[hh * 128 + lx + 32 * m4]  = qv;   // smem (swizzled)
                gq4[hh * 128 + lane + 32 * m4]  = qv;   // global (canonical)
            }
            if (hh == 0 && lane == 0) {
                acc_ne += 0.5f * (rmin - qd) - __logf(Zt);
                acc_qd += qd;
                idxs[n2p] = kmin;
            }
        }
        __syncthreads();

        // ====== phase 3: zq, warp = (slab, n-quad), lane = (ks, jg) =======
        {
            const int nbase = nq * 4;
            u64 acc[4][2];
            #pragma unroll
            for (int n2 = 0; n2 < 4; n2++) { acc[n2][0] = 0ull; acc[n2][1] = 0ull; }

            #pragma unroll
            for (int i4 = 0; i4 < 8; i4++) {
                const int kb = s3 * 128 + ks * 32 + i4 * 4;
                const int cx = ((s3 * 32 + ks * 8 + i4)) ^ ks;  // swizzled chunk
                float4 qv0 = ((const float4*)ds)[(nbase + 0) * 256 + cx];
                float4 qv1 = ((const float4*)ds)[(nbase + 1) * 256 + cx];
                float4 qv2 = ((const float4*)ds)[(nbase + 2) * 256 + cx];
                float4 qv3 = ((const float4*)ds)[(nbase + 3) * 256 + cx];
                #pragma unroll
                for (int e = 0; e < 4; e++) {
                    const float4 v = *(const float4*)(cbb + (kb + e) * 128 +
                        ((jg * 16) ^ (((kb + e) & 7) << 4)));
                    u64 cj0, cj1;
                    asm("mov.b64 %0, {%2, %3}; mov.b64 %1, {%4, %5};"
                        : "=l"(cj0), "=l"(cj1)
                        : "f"(v.x), "f"(v.y), "f"(v.z), "f"(v.w));
                    float q0 = (e == 0) ? qv0.x : (e == 1) ? qv0.y
                             : (e == 2) ? qv0.z : qv0.w;
                    float q1 = (e == 0) ? qv1.x : (e == 1) ? qv1.y
                             : (e == 2) ? qv1.z : qv1.w;
                    float q2 = (e == 0) ? qv2.x : (e == 1) ? qv2.y
                             : (e == 2) ? qv2.z : qv2.w;
                    float q3 = (e == 0) ? qv3.x : (e == 1) ? qv3.y
                             : (e == 2) ? qv3.z : qv3.w;
                    u64 d0 = dup2(q0), d1 = dup2(q1), d2 = dup2(q2), d3 = dup2(q3);
                    fma2(acc[0][0], d0, cj0); fma2(acc[0][1], d0, cj1);
                    fma2(acc[1][0], d1, cj0); fma2(acc[1][1], d1, cj1);
                    fma2(acc[2][0], d2, cj0); fma2(acc[2][1], d2, cj1);
                    fma2(acc[3][0], d3, cj0); fma2(acc[3][1], d3, cj1);
                }
            }
            // reduce across ks (lane bits 3,4)
            #pragma unroll
            for (int n2 = 0; n2 < 4; n2++) {
                acc[n2][0] = add2(acc[n2][0], shfl_xor64(acc[n2][0], 8));
                acc[n2][1] = add2(acc[n2][1], shfl_xor64(acc[n2][1], 8));
                acc[n2][0] = add2(acc[n2][0], shfl_xor64(acc[n2][0], 16));
                acc[n2][1] = add2(acc[n2][1], shfl_xor64(acc[n2][1], 16));
            }
            // lane stores row n2 = ks (select, no dynamic reg indexing)
            {
                u64 r0 = acc[0][0], r1 = acc[0][1];
                if (ks == 1) { r0 = acc[1][0]; r1 = acc[1][1]; }
                if (ks == 2) { r0 = acc[2][0]; r1 = acc[2][1]; }
                if (ks == 3) { r0 = acc[3][0]; r1 = acc[3][1]; }
                float a0, a1, a2, a3;
                unpk2(r0, a0, a1); unpk2(r1, a2, a3);
                *(float4*)(red + s3 * 512 + (nbase + ks) * 32 + jg * 4) =
                    make_float4(a0, a1, a2, a3);
            }

            // qbar partial (k = t, swizzled column)
            {
                const int kxq = dsx(t);
                float s0 = 0.0f;
                #pragma unroll
                for (int n2 = 0; n2 < 16; n2++) s0 += ds[n2 * 1024 + kxq];
                qbr += s0;
            }

            // quantized (hard codewords) + indices
            if (t < 512) {
                int n = nb + ni;
                int b = n >> 10;
                int kq = idxs[ni];
                out[(size_t)(b * 256 + c * 32 + jj) * 1024 + (n & 1023)] =
                    cb_el(cbb, kq, jj);
            }
            if (t < 16) {
                int n = nb + t;
                int b = n >> 10;
                out[O_IDX + (size_t)b * 8192 + c * 1024 + (n & 1023)] =
                    (float)idxs[t];
            }
            if (has_next && t < 512) {
                zft[(buf ^ 1) * 512 + jj * 16 + ni]  = zn;
                zftT[(buf ^ 1) * 528 + ni * 33 + jj] = zn;
                zsq_acc += zn * zn;
            }
        }
        __syncthreads();

        // ====== commitment: threads 0..511 <-> (n, j) =====================
        if (t < 512) {
            int n = t >> 5, j = t & 31;
            float s = 0.0f;
            #pragma unroll
            for (int ss = 0; ss < 8; ss++) s += red[ss * 512 + n * 32 + j];
            float diff = zftT[buf * 528 + n * 33 + j] - s;
            ct_comm = fmaf(diff, diff, ct_comm);
        }
        buf ^= 1;

        // ---- codebook switch (at most once per block) ----
        if (has_next && nc != c) {
            atomicAdd(&g_qbar[c * 1024 + t], qbr);
            qbr = 0.0f;
            __syncthreads();
            const float4* cb4 = (const float4*)(cbg + (size_t)nc * (KK * 32));
            #pragma unroll
            for (int it = 0; it < 8; it++) {
                int i = t + it * THREADS;
                float4 v = cb4[i];
                int k = i >> 3, j4 = i & 7;
                *(float4*)(cbb + k * 128 + ((j4 * 16) ^ ((k & 7) << 4))) = v;
            }
            __syncthreads();
            #pragma unroll
            for (int m = 0; m < 2; m++) {
                int k = k0 + 512 * m;
                float sq = 0.0f;
                #pragma unroll
                for (int j4 = 0; j4 < 8; j4++) {
                    float4 v = *cb_vec(cbb, k, j4);
                    sq += v.x * v.x + v.y * v.y + v.z * v.z + v.w * v.w;
                }
                cq[m] = sq;
            }
            c = nc;
        }
    }

    // ---- flush accumulators ----
    #pragma unroll
    for (int off = 16; off; off >>= 1) {
        ct_comm += __shfl_xor_sync(0xffffffffu, ct_comm, off);
        zsq_acc += __shfl_xor_sync(0xffffffffu, zsq_acc, off);
    }
    if (lane == 0) {
        atomicAdd(&g_comm, ct_comm);
        atomicAdd(&g_ne, acc_ne);
        atomicAdd(&g_qd, acc_qd + zsq_acc);
    }
    atomicAdd(&g_qbar[c * 1024 + t], qbr);

    // ---- last-block finalize (ticket) ----
    __threadfence();
    int* flag = (int*)(sm + OFF_IDX);
    if (t == 0) {
        unsigned int v = atomicAdd(&g_count, 1u);
        flag[16] = (v == (unsigned)(NBLOCKS - 1));
    }
    __syncthreads();
    if (flag[16]) {
        float local = 0.0f;
        #pragma unroll
        for (int it = 0; it < 8; it++) {
            int i = t + it * THREADS;
            float qb = g_qbar[i] * (1.0f / 4096.0f);
            local += qb * __logf(fmaf(qb, 1024.0f, 1e-8f));
            g_qbar[i] = 0.0f;                   // reset for next graph replay
        }
        #pragma unroll
        for (int off = 16; off; off >>= 1)
            local += __shfl_xor_sync(0xffffffffu, local, off);
        if (lane == 0) srm[w] = local;
        __syncthreads();
        if (t == 0) {
            float s = 0.0f;
            #pragma unroll
            for (int i = 0; i < 32; i++) s += srm[i];
            float balance = s * 0.125f;
            float comm = g_comm * (1.0f / 1048576.0f);
            float mne  = g_ne   * (1.0f / 32768.0f);
            float mqd  = g_qd   * (1.0f / 32768.0f);
            out[O_SC + 0] = comm;
            out[O_SC + 1] = fmaf(mqd, 0.5f, mne) + 6.93147180559945f;
            out[O_SC + 2] = -mne;
            out[O_SC + 3] = balance;
            out[O_SC + 4] = 1.0f;
            g_comm = 0.0f; g_ne = 0.0f; g_qd = 0.0f;
            g_count = 0u;
        }
    }
}

extern "C" void kernel_launch(void* const* d_in, const int* in_sizes, int n_in,
                              void* d_out, int out_size)
{
    const float* z   = (const float*)d_in[0];   // (4,256,32,32) f32
    const float* cbg = (const float*)d_in[1];   // (8,1024,32)  f32
    float* out = (float*)d_out;

    cudaFuncSetAttribute(lgq_main, cudaFuncAttributeMaxDynamicSharedMemorySize,
                         SMEM_BYTES);
    lgq_main<<<NBLOCKS, THREADS, SMEM_BYTES>>>(z, cbg, out);
}

// round 9
// speedup vs baseline: 1.0667x; 1.0667x over previous
#include <cuda_runtime.h>

typedef unsigned long long u64;

// ---------------- problem constants ----------------
#define CC 8
#define KK 1024
#define NT 8
#define THREADS 512
#define NBLOCKS 144            // 18 blocks per codebook -> zero cb switches
#define BPC 18
#define TPC 512                // 8n-tiles per codebook

// ---------------- smem layout (float offsets) ----------------
#define OFF_CB   0             // 32768: 1024 rows x 128B, SW128-swizzled
#define OFF_DS   32768         // 16384: 2 x [8 n][1024 k]  dists -> q
#define OFF_ZFT  49152         // 512:   2 x [32 j][8 n]
#define OFF_ZFTT 49664         // 792:   3 x [8 n][stride 33 j]
#define OFF_RED  50456         // 2048:  [8 slab][8 n][32 j]
#define OFF_IDX  52504         // 16 ints (2 x 8)
#define OFF_FLG  52520         // 1
#define OFF_SCR  52524         // 16
#define SMEM_FLOATS 52544
#define SMEM_BYTES (SMEM_FLOATS * 4)   // 210176 B

// ---------------- output packing (float32, tuple order) ----------------
#define O_IDX   1048576u
#define O_Q     1081344u
#define O_SC    34635776u

// ---------------- global scratch ----------------
__device__ float g_qbar[CC * KK];
__device__ float g_comm;
__device__ float g_ne;
__device__ float g_qd;
__device__ unsigned int g_count;

// ---------------- f32x2 helpers ----------------
__device__ __forceinline__ void fma2(u64 &d, u64 a, u64 b) {
    asm("fma.rn.f32x2 %0, %1, %2, %0;" : "+l"(d) : "l"(a), "l"(b));
}
__device__ __forceinline__ u64 add2(u64 a, u64 b) {
    u64 r; asm("add.rn.f32x2 %0, %1, %2;" : "=l"(r) : "l"(a), "l"(b)); return r;
}
__device__ __forceinline__ u64 dup2(float x) {
    u64 r; asm("mov.b64 %0, {%1, %1};" : "=l"(r) : "f"(x)); return r;
}
__device__ __forceinline__ u64 pk2(float lo, float hi) {
    u64 r; asm("mov.b64 %0, {%1, %2};" : "=l"(r) : "f"(lo), "f"(hi)); return r;
}
__device__ __forceinline__ void unpk2(u64 v, float &lo, float &hi) {
    asm("mov.b64 {%0, %1}, %2;" : "=f"(lo), "=f"(hi) : "l"(v));
}
__device__ __forceinline__ u64 shfl_xor64(u64 v, int m) {
    return __shfl_xor_sync(0xffffffffu, v, m);
}

// ---------------- swizzled codebook addressing (128B rows, SW128) ----------
__device__ __forceinline__ const float4* cb_vec(const char* cbb, int k, int j4) {
    return (const float4*)(cbb + k * 128 + ((j4 * 16) ^ ((k & 7) << 4)));
}
__device__ __forceinline__ float cb_el(const char* cbb, int k, int j) {
    return *(const float*)(cbb + k * 128 + ((j * 4) ^ ((k & 7) << 4)));
}

// ds column swizzle (float index involution): xor bits[3:2] with bits[6:5]
__device__ __forceinline__ int dsx(int i) { return i ^ ((i >> 3) & 12); }

__global__ void __launch_bounds__(THREADS, 1)
lgq_main(const float* __restrict__ z, const float* __restrict__ cbg,
         float* __restrict__ out)
{
    extern __shared__ float sm[];
    char*  cbb  = (char*)sm;
    float* ds   = sm + OFF_DS;
    float* zft  = sm + OFF_ZFT;
    float* zftT = sm + OFF_ZFTT;
    float* red  = sm + OFF_RED;
    int*   idxs = (int*)(sm + OFF_IDX);
    float* scr  = sm + OFF_SCR;

    const int t    = threadIdx.x;
    const int w    = t >> 5;
    const int lane = t & 31;
    const int bx   = blockIdx.x;

    const int c  = bx / BPC;
    const int bi = bx % BPC;
    const int s  = bi * 28 + min(bi, 8);           // tile range [s, e) in c
    const int e  = s + 28 + (bi < 8 ? 1 : 0);

    // ---- stage codebook c (swizzled) ----
    {
        const float4* cb4 = (const float4*)(cbg + (size_t)c * (KK * 32));
        #pragma unroll
        for (int it = 0; it < 16; it++) {
            int idx = t + it * THREADS;
            float4 v = cb4[idx];
            int k = idx >> 3, j4 = idx & 7;
            *(float4*)(cbb + k * 128 + ((j4 * 16) ^ ((k & 7) << 4))) = v;
        }
    }
    float zsq_acc = 0.0f;
    // ---- stage zf(tile s) ----
    if (t < 256) {
        int jj0 = t >> 3, ni0 = t & 7;
        int n = s * 8 + ni0, b = n >> 10;
        float v = z[(size_t)(b * 256 + c * 32 + jj0) * 1024 + (n & 1023)];
        zft[(s & 1) * 256 + jj0 * 8 + ni0]  = v;
        zftT[(s % 3) * 264 + ni0 * 33 + jj0] = v;
        zsq_acc = v * v;
    }
    __syncthreads();

    // ---- codeword norms for k0 + 256m (used by p1 warps) ----
    const int k0  = t & 255;
    const int kx0 = dsx(k0);
    float cq[4];
    #pragma unroll
    for (int m = 0; m < 4; m++) {
        int k = k0 + 256 * m;
        float sq = 0.0f;
        #pragma unroll
        for (int j4 = 0; j4 < 8; j4++) {
            float4 v = *cb_vec(cbb, k, j4);
            sq += v.x * v.x + v.y * v.y + v.z * v.z + v.w * v.w;
        }
        cq[m] = sq;
    }

    float acc_ne = 0.0f, acc_qd = 0.0f, ct_comm = 0.0f;
    float qbr0 = 0.0f, qbr1 = 0.0f, qbr2 = 0.0f, qbr3 = 0.0f;
    float zn = 0.0f;
    const int t2 = t - 256;    // consumer-group thread id (valid for w>=8)

    // =====================================================================
    // pipeline: iter i runs A:[p1(i+1) || p3(i)+LDG zf(i+2)]
    //                      B:[p2(i+1) || outputs(i)+STS zf(i+2)]
    // =====================================================================
    for (int i = s - 1; i < e; i++) {
        // ------------------------- Phase A ---------------------------
        if (w < 8) {
            if (i + 1 < e) {
                // p1: dists for tile i+1 -> ds[(i+1)&1]; thread = 4 k cols
                u64 acc[4][4];
                #pragma unroll
                for (int np = 0; np < 4; np++)
                    #pragma unroll
                    for (int m = 0; m < 4; m++) acc[np][m] = 0ull;

                const int sx = (k0 & 7) << 4;
                const float* zb = zft + ((i + 1) & 1) * 256;
                float* dsb = ds + ((i + 1) & 1) * 8192;

                #pragma unroll
                for (int j4 = 0; j4 < 8; j4++) {
                    const int off = (j4 * 16) ^ sx;
                    float4 cv0 = *(const float4*)(cbb + k0 * 128 + off);
                    float4 cv1 = *(const float4*)(cbb + (k0 + 256) * 128 + off);
                    float4 cv2 = *(const float4*)(cbb + (k0 + 512) * 128 + off);
                    float4 cv3 = *(const float4*)(cbb + (k0 + 768) * 128 + off);
                    #pragma unroll
                    for (int eI = 0; eI < 4; eI++) {
                        const ulonglong2* zp =
                            (const ulonglong2*)(zb + (j4 * 4 + eI) * 8);
                        ulonglong2 zA = zp[0], zB = zp[1];
                        float e0 = (eI == 0) ? cv0.x : (eI == 1) ? cv0.y
                                 : (eI == 2) ? cv0.z : cv0.w;
                        float e1 = (eI == 0) ? cv1.x : (eI == 1) ? cv1.y
                                 : (eI == 2) ? cv1.z : cv1.w;
                        float e2 = (eI == 0) ? cv2.x : (eI == 1) ? cv2.y
                                 : (eI == 2) ? cv2.z : cv2.w;
                        float e3 = (eI == 0) ? cv3.x : (eI == 1) ? cv3.y
                                 : (eI == 2) ? cv3.z : cv3.w;
                        u64 d0 = dup2(e0), d1 = dup2(e1);
                        u64 d2 = dup2(e2), d3 = dup2(e3);
                        fma2(acc[0][0], zA.x, d0); fma2(acc[0][1], zA.x, d1);
                        fma2(acc[0][2], zA.x, d2); fma2(acc[0][3], zA.x, d3);
                        fma2(acc[1][0], zA.y, d0); fma2(acc[1][1], zA.y, d1);
                        fma2(acc[1][2], zA.y, d2); fma2(acc[1][3], zA.y, d3);
                        fma2(acc[2][0], zB.x, d0); fma2(acc[2][1], zB.x, d1);
                        fma2(acc[2][2], zB.x, d2); fma2(acc[2][3], zB.x, d3);
                        fma2(acc[3][0], zB.y, d0); fma2(acc[3][1], zB.y, d1);
                        fma2(acc[3][2], zB.y, d2); fma2(acc[3][3], zB.y, d3);
                    }
                }
                #pragma unroll
                for (int np = 0; np < 4; np++)
                    #pragma unroll
                    for (int m = 0; m < 4; m++) {
                        float a, b2; unpk2(acc[np][m], a, b2);
                        int kx = kx0 + 256 * m;
                        dsb[(2 * np) * 1024 + kx]     = fmaf(-2.0f, a,  cq[m]);
                        dsb[(2 * np + 1) * 1024 + kx] = fmaf(-2.0f, b2, cq[m]);
                    }
            }
        } else {
            if (i >= s) {
                // p3: zq for tile i from q in ds[i&1]; warp = slab, lane=(ks,jg)
                const int s3 = w - 8;
                const int ks = lane >> 3;
                const int jg = lane & 7;
                const float* dsq = ds + (i & 1) * 8192;
                u64 acc[8][2];
                #pragma unroll
                for (int n2 = 0; n2 < 8; n2++) { acc[n2][0] = 0ull; acc[n2][1] = 0ull; }

                #pragma unroll
                for (int i4 = 0; i4 < 8; i4++) {
                    const int kb = s3 * 128 + ks * 32 + i4 * 4;
                    const int qc = (kb >> 2) ^ ks;
                    u64 cj0[4], cj1[4];
                    #pragma unroll
                    for (int eI = 0; eI < 4; eI++) {
                        const float4 v = *(const float4*)(cbb + (kb + eI) * 128 +
                            ((jg * 16) ^ (((kb + eI) & 7) << 4)));
                        cj0[eI] = pk2(v.x, v.y);
                        cj1[eI] = pk2(v.z, v.w);
                    }
                    #pragma unroll
                    for (int n2 = 0; n2 < 8; n2++) {
                        const float4 qv = ((const float4*)dsq)[n2 * 256 + qc];
                        u64 dx = dup2(qv.x), dy = dup2(qv.y);
                        u64 dz = dup2(qv.z), dw = dup2(qv.w);
                        fma2(acc[n2][0], dx, cj0[0]); fma2(acc[n2][1], dx, cj1[0]);
                        fma2(acc[n2][0], dy, cj0[1]); fma2(acc[n2][1], dy, cj1[1]);
                        fma2(acc[n2][0], dz, cj0[2]); fma2(acc[n2][1], dz, cj1[2]);
                        fma2(acc[n2][0], dw, cj0[3]); fma2(acc[n2][1], dw, cj1[3]);
                    }
                }
                #pragma unroll
                for (int n2 = 0; n2 < 8; n2++) {
                    acc[n2][0] = add2(acc[n2][0], shfl_xor64(acc[n2][0], 8));
                    acc[n2][1] = add2(acc[n2][1], shfl_xor64(acc[n2][1], 8));
                    acc[n2][0] = add2(acc[n2][0], shfl_xor64(acc[n2][0], 16));
                    acc[n2][1] = add2(acc[n2][1], shfl_xor64(acc[n2][1], 16));
                }
                // lane (ks) stores rows ks*2, ks*2+1 — explicit select
                u64 r0a = acc[0][0], r1a = acc[0][1];
                u64 r0b = acc[1][0], r1b = acc[1][1];
                if (ks == 1) { r0a = acc[2][0]; r1a = acc[2][1];
                               r0b = acc[3][0]; r1b = acc[3][1]; }
                if (ks == 2) { r0a = acc[4][0]; r1a = acc[4][1];
                               r0b = acc[5][0]; r1b = acc[5][1]; }
                if (ks == 3) { r0a = acc[6][0]; r1a = acc[6][1];
                               r0b = acc[7][0]; r1b = acc[7][1]; }
                float a0, a1, a2, a3;
                unpk2(r0a, a0, a1); unpk2(r1a, a2, a3);
                *(float4*)(red + s3 * 256 + (ks * 2) * 32 + jg * 4) =
                    make_float4(a0, a1, a2, a3);
                unpk2(r0b, a0, a1); unpk2(r1b, a2, a3);
                *(float4*)(red + s3 * 256 + (ks * 2 + 1) * 32 + jg * 4) =
                    make_float4(a0, a1, a2, a3);
            }
            if (i + 2 < e) {
                int jj2 = t2 >> 3, ni2 = t2 & 7;
                int n = (i + 2) * 8 + ni2, b = n >> 10;
                zn = z[(size_t)(b * 256 + c * 32 + jj2) * 1024 + (n & 1023)];
            }
        }
        __syncthreads();

        // ------------------------- Phase B ---------------------------
        if (w < 8) {
            if (i + 1 < e) {
                // p2: softmax/argmin for tile i+1, warp w <-> row w
                const int lx = lane ^ ((lane >> 3) & 3);
                float* row = ds + ((i + 1) & 1) * 8192 + w * 1024;
                const float4* row4  = (const float4*)row;
                float4*       row4w = (float4*)row;
                float dv[32];
                #pragma unroll
                for (int m4 = 0; m4 < 8; m4++) {
                    float4 v = row4[lx + 32 * m4];
                    dv[m4 * 4 + 0] = v.x; dv[m4 * 4 + 1] = v.y;
                    dv[m4 * 4 + 2] = v.z; dv[m4 * 4 + 3] = v.w;
                }
                float rmin = 3.4e38f; int kmin = 1 << 30;
                #pragma unroll
                for (int ii = 0; ii < 32; ii++) {
                    int k = 4 * lane + 128 * (ii >> 2) + (ii & 3);
                    float dd = dv[ii];
                    if (dd < rmin || (dd == rmin && k < kmin)) { rmin = dd; kmin = k; }
                }
                #pragma unroll
                for (int off = 16; off; off >>= 1) {
                    float od = __shfl_xor_sync(0xffffffffu, rmin, off);
                    int   ok = __shfl_xor_sync(0xffffffffu, kmin, off);
                    if (od < rmin || (od == rmin && ok < kmin)) { rmin = od; kmin = ok; }
                }
                float Z = 0.0f, sed = 0.0f;
                #pragma unroll
                for (int ii = 0; ii < 32; ii++) {
                    float told = dv[ii];
                    float ev = __expf((rmin - told) * 0.5f);
                    Z += ev;
                    sed = fmaf(ev, told, sed);
                    dv[ii] = ev;
                }
                #pragma unroll
                for (int off = 16; off; off >>= 1) {
                    Z   += __shfl_xor_sync(0xffffffffu, Z, off);
                    sed += __shfl_xor_sync(0xffffffffu, sed, off);
                }
                float rZ = __fdividef(1.0f, Z);
                float qd = sed * rZ;

                int n = (i + 1) * 8 + w;
                float4* gq4 = (float4*)(out + O_Q + ((size_t)n * 8 + c) * 1024);
                #pragma unroll
                for (int m4 = 0; m4 < 8; m4++) {
                    float4 qv;
                    qv.x = dv[m4 * 4 + 0] * rZ; qv.y = dv[m4 * 4 + 1] * rZ;
                    qv.z = dv[m4 * 4 + 2] * rZ; qv.w = dv[m4 * 4 + 3] * rZ;
                    row4w[lx + 32 * m4] = qv;
                    gq4[lane + 32 * m4] = qv;
                }
                if (lane == 0) {
                    acc_ne += 0.5f * (rmin - qd) - __logf(Z);
                    acc_qd += qd;
                    idxs[((i + 1) & 1) * 8 + w] = kmin;
                }
            }
        } else {
            if (i >= s) {
                const float* dsq = ds + (i & 1) * 8192;
                // qbar partials for k = t2 + 256m
                const int kxq = dsx(t2);
                float s0 = 0.0f, s1 = 0.0f, s2 = 0.0f, s3p = 0.0f;
                #pragma unroll
                for (int n2 = 0; n2 < 8; n2++) {
                    s0  += dsq[n2 * 1024 + kxq];
                    s1  += dsq[n2 * 1024 + kxq + 256];
                    s2  += dsq[n2 * 1024 + kxq + 512];
                    s3p += dsq[n2 * 1024 + kxq + 768];
                }
                qbr0 += s0; qbr1 += s1; qbr2 += s2; qbr3 += s3p;

                // quantized (hard codewords)
                {
                    int ni0 = t2 & 7, jq = t2 >> 3;
                    int n = i * 8 + ni0, b = n >> 10;
                    int kq = idxs[(i & 1) * 8 + ni0];
                    out[(size_t)(b * 256 + c * 32 + jq) * 1024 + (n & 1023)] =
                        cb_el(cbb, kq, jq);
                }
                if (t2 < 8) {
                    int n = i * 8 + t2, b = n >> 10;
                    out[O_IDX + (size_t)b * 8192 + c * 1024 + (n & 1023)] =
                        (float)idxs[(i & 1) * 8 + t2];
                }
                // commitment
                {
                    int cn = t2 >> 5, cj = t2 & 31;
                    float sr = 0.0f;
                    #pragma unroll
                    for (int ss = 0; ss < 8; ss++)
                        sr += red[ss * 256 + cn * 32 + cj];
                    float diff = zftT[(i % 3) * 264 + cn * 33 + cj] - sr;
                    ct_comm = fmaf(diff, diff, ct_comm);
                }
            }
            if (i + 2 < e) {
                int jj2 = t2 >> 3, ni2 = t2 & 7;
                zft[(i & 1) * 256 + jj2 * 8 + ni2]        = zn;   // (i+2)&1 == i&1
                zftT[((i + 2) % 3) * 264 + ni2 * 33 + jj2] = zn;
                zsq_acc += zn * zn;
            }
        }
        __syncthreads();
    }

    // ---- flush accumulators ----
    #pragma unroll
    for (int off = 16; off; off >>= 1) {
        ct_comm += __shfl_xor_sync(0xffffffffu, ct_comm, off);
        zsq_acc += __shfl_xor_sync(0xffffffffu, zsq_acc, off);
    }
    if (lane == 0) {
        atomicAdd(&g_comm, ct_comm);
        atomicAdd(&g_qd, zsq_acc + ((w < 8) ? acc_qd : 0.0f));
        if (w < 8) atomicAdd(&g_ne, acc_ne);
    }
    if (w >= 8) {
        atomicAdd(&g_qbar[c * 1024 + t2],       qbr0);
        atomicAdd(&g_qbar[c * 1024 + t2 + 256], qbr1);
        atomicAdd(&g_qbar[c * 1024 + t2 + 512], qbr2);
        atomicAdd(&g_qbar[c * 1024 + t2 + 768], qbr3);
    }

    // ---- last-block finalize (ticket) ----
    __threadfence();
    int* flag = (int*)(sm + OFF_FLG);
    if (t == 0) {
        unsigned int v = atomicAdd(&g_count, 1u);
        flag[0] = (v == (unsigned)(NBLOCKS - 1));
    }
    __syncthreads();
    if (flag[0]) {
        float local = 0.0f;
        #pragma unroll
        for (int it = 0; it < 16; it++) {
            int idx = t + it * THREADS;
            float qb = g_qbar[idx] * (1.0f / 4096.0f);
            local += qb * __logf(fmaf(qb, 1024.0f, 1e-8f));
            g_qbar[idx] = 0.0f;                 // reset for next graph replay
        }
        #pragma unroll
        for (int off = 16; off; off >>= 1)
            local += __shfl_xor_sync(0xffffffffu, local, off);
        if (lane == 0) scr[w] = local;
        __syncthreads();
        if (t == 0) {
            float sr = 0.0f;
            #pragma unroll
            for (int ii = 0; ii < 16; ii++) sr += scr[ii];
            float balance = sr * 0.125f;
            float comm = g_comm * (1.0f / 1048576.0f);
            float mne  = g_ne   * (1.0f / 32768.0f);
            float mqd  = g_qd   * (1.0f / 32768.0f);
            out[O_SC + 0] = comm;
            out[O_SC + 1] = fmaf(mqd, 0.5f, mne) + 6.93147180559945f;
            out[O_SC + 2] = -mne;
            out[O_SC + 3] = balance;
            out[O_SC + 4] = 1.0f;
            g_comm = 0.0f; g_ne = 0.0f; g_qd = 0.0f;
            g_count = 0u;
        }
    }
}

extern "C" void kernel_launch(void* const* d_in, const int* in_sizes, int n_in,
                              void* d_out, int out_size)
{
    const float* z   = (const float*)d_in[0];   // (4,256,32,32) f32
    const float* cbg = (const float*)d_in[1];   // (8,1024,32)  f32
    float* out = (float*)d_out;

    cudaFuncSetAttribute(lgq_main, cudaFuncAttributeMaxDynamicSharedMemorySize,
                         SMEM_BYTES);
    lgq_main<<<NBLOCKS, THREADS, SMEM_BYTES>>>(z, cbg, out);
}

// round 10
// speedup vs baseline: 1.0732x; 1.0061x over previous
#include <cuda_runtime.h>

typedef unsigned long long u64;

// ---------------- problem constants ----------------
#define CC 8
#define KK 1024
#define NT 8
#define THREADS 512
#define NBLOCKS 144            // 18 blocks per codebook -> zero cb switches
#define BPC 18
#define TPC 512                // 8n-tiles per codebook

// ---------------- smem layout (float offsets) ----------------
#define OFF_CB   0             // 32768: 1024 rows x 128B, SW128-swizzled
#define OFF_DS   32768         // 16384: 2 x [8 n][1024 k]  dists -> q
#define OFF_ZFT  49152         // 512:   2 x [32 j][8 n]
#define OFF_ZFTT 49664         // 792:   3 x [8 n][stride 33 j]
#define OFF_RED  50456         // 2048:  [8 slab][8 n][32 j]
#define OFF_IDX  52504         // 16 ints (2 x 8)
#define OFF_FLG  52520         // 1
#define OFF_SCR  52524         // 16
#define SMEM_FLOATS 52544
#define SMEM_BYTES (SMEM_FLOATS * 4)   // 210176 B

// ---------------- output packing (float32, tuple order) ----------------
#define O_IDX   1048576u
#define O_Q     1081344u
#define O_SC    34635776u

// ---------------- global scratch ----------------
__device__ float g_qbar[CC * KK];
__device__ float g_comm;
__device__ float g_ne;
__device__ float g_qd;
__device__ unsigned int g_count;

// ---------------- f32x2 helpers ----------------
__device__ __forceinline__ void fma2(u64 &d, u64 a, u64 b) {
    asm("fma.rn.f32x2 %0, %1, %2, %0;" : "+l"(d) : "l"(a), "l"(b));
}
__device__ __forceinline__ u64 add2(u64 a, u64 b) {
    u64 r; asm("add.rn.f32x2 %0, %1, %2;" : "=l"(r) : "l"(a), "l"(b)); return r;
}
__device__ __forceinline__ u64 dup2(float x) {
    u64 r; asm("mov.b64 %0, {%1, %1};" : "=l"(r) : "f"(x)); return r;
}
__device__ __forceinline__ u64 pk2(float lo, float hi) {
    u64 r; asm("mov.b64 %0, {%1, %2};" : "=l"(r) : "f"(lo), "f"(hi)); return r;
}
__device__ __forceinline__ void unpk2(u64 v, float &lo, float &hi) {
    asm("mov.b64 {%0, %1}, %2;" : "=f"(lo), "=f"(hi) : "l"(v));
}
__device__ __forceinline__ u64 shfl_xor64(u64 v, int m) {
    return __shfl_xor_sync(0xffffffffu, v, m);
}

// ---------------- swizzled codebook addressing (128B rows, SW128) ----------
__device__ __forceinline__ const float4* cb_vec(const char* cbb, int k, int j4) {
    return (const float4*)(cbb + k * 128 + ((j4 * 16) ^ ((k & 7) << 4)));
}
__device__ __forceinline__ float cb_el(const char* cbb, int k, int j) {
    return *(const float*)(cbb + k * 128 + ((j * 4) ^ ((k & 7) << 4)));
}

// ds column swizzle (float index involution): xor bits[3:2] with bits[6:5]
__device__ __forceinline__ int dsx(int i) { return i ^ ((i >> 3) & 12); }

__global__ void __launch_bounds__(THREADS, 1)
lgq_main(const float* __restrict__ z, const float* __restrict__ cbg,
         float* __restrict__ out)
{
    extern __shared__ float sm[];
    char*  cbb  = (char*)sm;
    float* ds   = sm + OFF_DS;
    float* zft  = sm + OFF_ZFT;
    float* zftT = sm + OFF_ZFTT;
    float* red  = sm + OFF_RED;
    int*   idxs = (int*)(sm + OFF_IDX);
    float* scr  = sm + OFF_SCR;

    const int t    = threadIdx.x;
    const int w    = t >> 5;
    const int lane = t & 31;
    const int bx   = blockIdx.x;

    const int c  = bx / BPC;
    const int bi = bx % BPC;
    const int s  = bi * 28 + min(bi, 8);           // tile range [s, e) in c
    const int e  = s + 28 + (bi < 8 ? 1 : 0);

    // ---- stage codebook c (swizzled) ----
    {
        const float4* cb4 = (const float4*)(cbg + (size_t)c * (KK * 32));
        #pragma unroll
        for (int it = 0; it < 16; it++) {
            int idx = t + it * THREADS;
            float4 v = cb4[idx];
            int k = idx >> 3, j4 = idx & 7;
            *(float4*)(cbb + k * 128 + ((j4 * 16) ^ ((k & 7) << 4))) = v;
        }
    }
    float zsq_acc = 0.0f;
    // ---- stage zf(tile s) ----
    if (t < 256) {
        int jj0 = t >> 3, ni0 = t & 7;
        int n = s * 8 + ni0, b = n >> 10;
        float v = z[(size_t)(b * 256 + c * 32 + jj0) * 1024 + (n & 1023)];
        zft[(s & 1) * 256 + jj0 * 8 + ni0]  = v;
        zftT[(s % 3) * 264 + ni0 * 33 + jj0] = v;
        zsq_acc = v * v;
    }
    __syncthreads();

    // ---- codeword norms for k0 + 256m (used by p1 warps) ----
    const int k0  = t & 255;
    const int kx0 = dsx(k0);
    float cq[4];
    #pragma unroll
    for (int m = 0; m < 4; m++) {
        int k = k0 + 256 * m;
        float sq = 0.0f;
        #pragma unroll
        for (int j4 = 0; j4 < 8; j4++) {
            float4 v = *cb_vec(cbb, k, j4);
            sq += v.x * v.x + v.y * v.y + v.z * v.z + v.w * v.w;
        }
        cq[m] = sq;
    }

    float acc_ne = 0.0f, acc_qd = 0.0f, ct_comm = 0.0f;
    float qbr0 = 0.0f, qbr1 = 0.0f, qbr2 = 0.0f, qbr3 = 0.0f;
    float zn = 0.0f;
    const int t2 = t - 256;    // consumer-group thread id (valid for w>=8)

    // =====================================================================
    // pipeline: iter i runs A:[p1(i+1) || p3(i)+LDG zf(i+2)]
    //                      B:[p2(i+1) || outputs(i)+STS zf(i+2)]
    // =====================================================================
    for (int i = s - 1; i < e; i++) {
        // ------------------------- Phase A ---------------------------
        if (w < 8) {
            if (i + 1 < e) {
                // p1: dists for tile i+1 -> ds[(i+1)&1]; thread = 4 k cols
                u64 acc[4][4];
                #pragma unroll
                for (int np = 0; np < 4; np++)
                    #pragma unroll
                    for (int m = 0; m < 4; m++) acc[np][m] = 0ull;

                const int sx = (k0 & 7) << 4;
                const float* zb = zft + ((i + 1) & 1) * 256;
                float* dsb = ds + ((i + 1) & 1) * 8192;

                #pragma unroll
                for (int j4 = 0; j4 < 8; j4++) {
                    const int off = (j4 * 16) ^ sx;
                    float4 cv0 = *(const float4*)(cbb + k0 * 128 + off);
                    float4 cv1 = *(const float4*)(cbb + (k0 + 256) * 128 + off);
                    float4 cv2 = *(const float4*)(cbb + (k0 + 512) * 128 + off);
                    float4 cv3 = *(const float4*)(cbb + (k0 + 768) * 128 + off);
                    #pragma unroll
                    for (int eI = 0; eI < 4; eI++) {
                        const ulonglong2* zp =
                            (const ulonglong2*)(zb + (j4 * 4 + eI) * 8);
                        ulonglong2 zA = zp[0], zB = zp[1];
                        float e0 = (eI == 0) ? cv0.x : (eI == 1) ? cv0.y
                                 : (eI == 2) ? cv0.z : cv0.w;
                        float e1 = (eI == 0) ? cv1.x : (eI == 1) ? cv1.y
                                 : (eI == 2) ? cv1.z : cv1.w;
                        float e2 = (eI == 0) ? cv2.x : (eI == 1) ? cv2.y
                                 : (eI == 2) ? cv2.z : cv2.w;
                        float e3 = (eI == 0) ? cv3.x : (eI == 1) ? cv3.y
                                 : (eI == 2) ? cv3.z : cv3.w;
                        u64 d0 = dup2(e0), d1 = dup2(e1);
                        u64 d2 = dup2(e2), d3 = dup2(e3);
                        fma2(acc[0][0], zA.x, d0); fma2(acc[0][1], zA.x, d1);
                        fma2(acc[0][2], zA.x, d2); fma2(acc[0][3], zA.x, d3);
                        fma2(acc[1][0], zA.y, d0); fma2(acc[1][1], zA.y, d1);
                        fma2(acc[1][2], zA.y, d2); fma2(acc[1][3], zA.y, d3);
                        fma2(acc[2][0], zB.x, d0); fma2(acc[2][1], zB.x, d1);
                        fma2(acc[2][2], zB.x, d2); fma2(acc[2][3], zB.x, d3);
                        fma2(acc[3][0], zB.y, d0); fma2(acc[3][1], zB.y, d1);
                        fma2(acc[3][2], zB.y, d2); fma2(acc[3][3], zB.y, d3);
                    }
                }
                #pragma unroll
                for (int np = 0; np < 4; np++)
                    #pragma unroll
                    for (int m = 0; m < 4; m++) {
                        float a, b2; unpk2(acc[np][m], a, b2);
                        int kx = kx0 + 256 * m;
                        dsb[(2 * np) * 1024 + kx]     = fmaf(-2.0f, a,  cq[m]);
                        dsb[(2 * np + 1) * 1024 + kx] = fmaf(-2.0f, b2, cq[m]);
                    }
            }
        } else {
            if (i >= s) {
                // p3: zq for tile i from q in ds[i&1]; warp = slab, lane=(ks,jg)
                const int s3 = w - 8;
                const int ks = lane >> 3;
                const int jg = lane & 7;
                const float* dsq = ds + (i & 1) * 8192;
                u64 acc[8][2];
                #pragma unroll
                for (int n2 = 0; n2 < 8; n2++) { acc[n2][0] = 0ull; acc[n2][1] = 0ull; }

                #pragma unroll
                for (int i4 = 0; i4 < 8; i4++) {
                    const int kb = s3 * 128 + ks * 32 + i4 * 4;
                    const int qc = (kb >> 2) ^ ks;
                    u64 cj0[4], cj1[4];
                    #pragma unroll
                    for (int eI = 0; eI < 4; eI++) {
                        const float4 v = *(const float4*)(cbb + (kb + eI) * 128 +
                            ((jg * 16) ^ (((kb + eI) & 7) << 4)));
                        cj0[eI] = pk2(v.x, v.y);
                        cj1[eI] = pk2(v.z, v.w);
                    }
                    #pragma unroll
                    for (int n2 = 0; n2 < 8; n2++) {
                        const float4 qv = ((const float4*)dsq)[n2 * 256 + qc];
                        u64 dx = dup2(qv.x), dy = dup2(qv.y);
                        u64 dz = dup2(qv.z), dw = dup2(qv.w);
                        fma2(acc[n2][0], dx, cj0[0]); fma2(acc[n2][1], dx, cj1[0]);
                        fma2(acc[n2][0], dy, cj0[1]); fma2(acc[n2][1], dy, cj1[1]);
                        fma2(acc[n2][0], dz, cj0[2]); fma2(acc[n2][1], dz, cj1[2]);
                        fma2(acc[n2][0], dw, cj0[3]); fma2(acc[n2][1], dw, cj1[3]);
                    }
                }
                #pragma unroll
                for (int n2 = 0; n2 < 8; n2++) {
                    acc[n2][0] = add2(acc[n2][0], shfl_xor64(acc[n2][0], 8));
                    acc[n2][1] = add2(acc[n2][1], shfl_xor64(acc[n2][1], 8));
                    acc[n2][0] = add2(acc[n2][0], shfl_xor64(acc[n2][0], 16));
                    acc[n2][1] = add2(acc[n2][1], shfl_xor64(acc[n2][1], 16));
                }
                // lane (ks) stores rows ks*2, ks*2+1 — explicit select
                u64 r0a = acc[0][0], r1a = acc[0][1];
                u64 r0b = acc[1][0], r1b = acc[1][1];
                if (ks == 1) { r0a = acc[2][0]; r1a = acc[2][1];
                               r0b = acc[3][0]; r1b = acc[3][1]; }
                if (ks == 2) { r0a = acc[4][0]; r1a = acc[4][1];
                               r0b = acc[5][0]; r1b = acc[5][1]; }
                if (ks == 3) { r0a = acc[6][0]; r1a = acc[6][1];
                               r0b = acc[7][0]; r1b = acc[7][1]; }
                float a0, a1, a2, a3;
                unpk2(r0a, a0, a1); unpk2(r1a, a2, a3);
                *(float4*)(red + s3 * 256 + (ks * 2) * 32 + jg * 4) =
                    make_float4(a0, a1, a2, a3);
                unpk2(r0b, a0, a1); unpk2(r1b, a2, a3);
                *(float4*)(red + s3 * 256 + (ks * 2 + 1) * 32 + jg * 4) =
                    make_float4(a0, a1, a2, a3);
            }
            if (i + 2 < e) {
                int jj2 = t2 >> 3, ni2 = t2 & 7;
                int n = (i + 2) * 8 + ni2, b = n >> 10;
                zn = z[(size_t)(b * 256 + c * 32 + jj2) * 1024 + (n & 1023)];
            }
        }
        __syncthreads();

        // ------------------------- Phase B ---------------------------
        if (w < 8) {
            if (i + 1 < e) {
                // p2: softmax/argmin for tile i+1, warp w <-> row w
                const int lx = lane ^ ((lane >> 3) & 3);
                float* row = ds + ((i + 1) & 1) * 8192 + w * 1024;
                const float4* row4  = (const float4*)row;
                float4*       row4w = (float4*)row;
                float dv[32];
                #pragma unroll
                for (int m4 = 0; m4 < 8; m4++) {
                    float4 v = row4[lx + 32 * m4];
                    dv[m4 * 4 + 0] = v.x; dv[m4 * 4 + 1] = v.y;
                    dv[m4 * 4 + 2] = v.z; dv[m4 * 4 + 3] = v.w;
                }
                float rmin = 3.4e38f; int kmin = 1 << 30;
                #pragma unroll
                for (int ii = 0; ii < 32; ii++) {
                    int k = 4 * lane + 128 * (ii >> 2) + (ii & 3);
                    float dd = dv[ii];
                    if (dd < rmin || (dd == rmin && k < kmin)) { rmin = dd; kmin = k; }
                }
                #pragma unroll
                for (int off = 16; off; off >>= 1) {
                    float od = __shfl_xor_sync(0xffffffffu, rmin, off);
                    int   ok = __shfl_xor_sync(0xffffffffu, kmin, off);
                    if (od < rmin || (od == rmin && ok < kmin)) { rmin = od; kmin = ok; }
                }
                float Z = 0.0f, sed = 0.0f;
                #pragma unroll
                for (int ii = 0; ii < 32; ii++) {
                    float told = dv[ii];
                    float ev = __expf((rmin - told) * 0.5f);
                    Z += ev;
                    sed = fmaf(ev, told, sed);
                    dv[ii] = ev;
                }
                #pragma unroll
                for (int off = 16; off; off >>= 1) {
                    Z   += __shfl_xor_sync(0xffffffffu, Z, off);
                    sed += __shfl_xor_sync(0xffffffffu, sed, off);
                }
                float rZ = __fdividef(1.0f, Z);
                float qd = sed * rZ;

                int n = (i + 1) * 8 + w;
                float4* gq4 = (float4*)(out + O_Q + ((size_t)n * 8 + c) * 1024);
                #pragma unroll
                for (int m4 = 0; m4 < 8; m4++) {
                    float4 qv;
                    qv.x = dv[m4 * 4 + 0] * rZ; qv.y = dv[m4 * 4 + 1] * rZ;
                    qv.z = dv[m4 * 4 + 2] * rZ; qv.w = dv[m4 * 4 + 3] * rZ;
                    row4w[lx + 32 * m4] = qv;
                    gq4[lane + 32 * m4] = qv;
                }
                if (lane == 0) {
                    acc_ne += 0.5f * (rmin - qd) - __logf(Z);
                    acc_qd += qd;
                    idxs[((i + 1) & 1) * 8 + w] = kmin;
                }
            }
        } else {
            if (i >= s) {
                const float* dsq = ds + (i & 1) * 8192;
                // qbar partials for k = t2 + 256m
                const int kxq = dsx(t2);
                float s0 = 0.0f, s1 = 0.0f, s2 = 0.0f, s3p = 0.0f;
                #pragma unroll
                for (int n2 = 0; n2 < 8; n2++) {
                    s0  += dsq[n2 * 1024 + kxq];
                    s1  += dsq[n2 * 1024 + kxq + 256];
                    s2  += dsq[n2 * 1024 + kxq + 512];
                    s3p += dsq[n2 * 1024 + kxq + 768];
                }
                qbr0 += s0; qbr1 += s1; qbr2 += s2; qbr3 += s3p;

                // quantized (hard codewords)
                {
                    int ni0 = t2 & 7, jq = t2 >> 3;
                    int n = i * 8 + ni0, b = n >> 10;
                    int kq = idxs[(i & 1) * 8 + ni0];
                    out[(size_t)(b * 256 + c * 32 + jq) * 1024 + (n & 1023)] =
                        cb_el(cbb, kq, jq);
                }
                if (t2 < 8) {
                    int n = i * 8 + t2, b = n >> 10;
                    out[O_IDX + (size_t)b * 8192 + c * 1024 + (n & 1023)] =
                        (float)idxs[(i & 1) * 8 + t2];
                }
                // commitment
                {
                    int cn = t2 >> 5, cj = t2 & 31;
                    float sr = 0.0f;
                    #pragma unroll
                    for (int ss = 0; ss < 8; ss++)
                        sr += red[ss * 256 + cn * 32 + cj];
                    float diff = zftT[(i % 3) * 264 + cn * 33 + cj] - sr;
                    ct_comm = fmaf(diff, diff, ct_comm);
                }
            }
            if (i + 2 < e) {
                int jj2 = t2 >> 3, ni2 = t2 & 7;
                zft[(i & 1) * 256 + jj2 * 8 + ni2]        = zn;   // (i+2)&1 == i&1
                zftT[((i + 2) % 3) * 264 + ni2 * 33 + jj2] = zn;
                zsq_acc += zn * zn;
            }
        }
        __syncthreads();
    }

    // ---- flush accumulators ----
    #pragma unroll
    for (int off = 16; off; off >>= 1) {
        ct_comm += __shfl_xor_sync(0xffffffffu, ct_comm, off);
        zsq_acc += __shfl_xor_sync(0xffffffffu, zsq_acc, off);
    }
    if (lane == 0) {
        atomicAdd(&g_comm, ct_comm);
        atomicAdd(&g_qd, zsq_acc + ((w < 8) ? acc_qd : 0.0f));
        if (w < 8) atomicAdd(&g_ne, acc_ne);
    }
    if (w >= 8) {
        atomicAdd(&g_qbar[c * 1024 + t2],       qbr0);
        atomicAdd(&g_qbar[c * 1024 + t2 + 256], qbr1);
        atomicAdd(&g_qbar[c * 1024 + t2 + 512], qbr2);
        atomicAdd(&g_qbar[c * 1024 + t2 + 768], qbr3);
    }

    // ---- last-block finalize (ticket) ----
    __threadfence();
    int* flag = (int*)(sm + OFF_FLG);
    if (t == 0) {
        unsigned int v = atomicAdd(&g_count, 1u);
        flag[0] = (v == (unsigned)(NBLOCKS - 1));
    }
    __syncthreads();
    if (flag[0]) {
        float local = 0.0f;
        #pragma unroll
        for (int it = 0; it < 16; it++) {
            int idx = t + it * THREADS;
            float qb = g_qbar[idx] * (1.0f / 4096.0f);
            local += qb * __logf(fmaf(qb, 1024.0f, 1e-8f));
            g_qbar[idx] = 0.0f;                 // reset for next graph replay
        }
        #pragma unroll
        for (int off = 16; off; off >>= 1)
            local += __shfl_xor_sync(0xffffffffu, local, off);
        if (lane == 0) scr[w] = local;
        __syncthreads();
        if (t == 0) {
            float sr = 0.0f;
            #pragma unroll
            for (int ii = 0; ii < 16; ii++) sr += scr[ii];
            float balance = sr * 0.125f;
            float comm = g_comm * (1.0f / 1048576.0f);
            float mne  = g_ne   * (1.0f / 32768.0f);
            float mqd  = g_qd   * (1.0f / 32768.0f);
            out[O_SC + 0] = comm;
            out[O_SC + 1] = fmaf(mqd, 0.5f, mne) + 6.93147180559945f;
            out[O_SC + 2] = -mne;
            out[O_SC + 3] = balance;
            out[O_SC + 4] = 1.0f;
            g_comm = 0.0f; g_ne = 0.0f; g_qd = 0.0f;
            g_count = 0u;
        }
    }
}

extern "C" void kernel_launch(void* const* d_in, const int* in_sizes, int n_in,
                              void* d_out, int out_size)
{
    const float* z   = (const float*)d_in[0];   // (4,256,32,32) f32
    const float* cbg = (const float*)d_in[1];   // (8,1024,32)  f32
    float* out = (float*)d_out;

    cudaFuncSetAttribute(lgq_main, cudaFuncAttributeMaxDynamicSharedMemorySize,
                         SMEM_BYTES);
    lgq_main<<<NBLOCKS, THREADS, SMEM_BYTES>>>(z, cbg, out);
}

// round 11
// speedup vs baseline: 1.1026x; 1.0274x over previous
#include <cuda_runtime.h>

typedef unsigned long long u64;

// ---------------- problem constants ----------------
#define CC 8
#define KK 1024
#define THREADS 512
#define NBLOCKS 144            // 18 blocks per codebook, zero cb switches
#define BPC 18

// ---------------- smem layout (float offsets) ----------------
#define OFF_CB   0             // 32768: 1024 rows x 128B, SW128-swizzled
#define OFF_DS   32768         // 16384: 2 x [8 n][1024 k] dists (canonical)
#define OFF_ZFT  49152         // 512:   2 x [32 j][8 n]
#define OFF_ZFTT 49664         // 1320:  5 x [8 n][stride 33 j]
#define OFF_RED  50984         // 4096:  2 x [8 slab][8 n][32 j]
#define OFF_IDX  55080         // 24 ints (3 x 8)
#define OFF_FLG  55104         // 1
#define OFF_SCR  55108         // 16
#define SMEM_FLOATS 55124
#define SMEM_BYTES (SMEM_FLOATS * 4)   // 220496 B

// ---------------- output packing (float32, tuple order) ----------------
#define O_IDX   1048576u
#define O_Q     1081344u
#define O_SC    34635776u

// ---------------- global scratch ----------------
__device__ float g_qbar[CC * KK];
__device__ float g_comm;
__device__ float g_ne;
__device__ float g_qd;
__device__ unsigned int g_count;

// ---------------- f32x2 helpers ----------------
__device__ __forceinline__ void fma2(u64 &d, u64 a, u64 b) {
    asm("fma.rn.f32x2 %0, %1, %2, %0;" : "+l"(d) : "l"(a), "l"(b));
}
__device__ __forceinline__ u64 add2(u64 a, u64 b) {
    u64 r; asm("add.rn.f32x2 %0, %1, %2;" : "=l"(r) : "l"(a), "l"(b)); return r;
}
__device__ __forceinline__ u64 dup2(float x) {
    u64 r; asm("mov.b64 %0, {%1, %1};" : "=l"(r) : "f"(x)); return r;
}
__device__ __forceinline__ u64 pk2(float lo, float hi) {
    u64 r; asm("mov.b64 %0, {%1, %2};" : "=l"(r) : "f"(lo), "f"(hi)); return r;
}
__device__ __forceinline__ void unpk2(u64 v, float &lo, float &hi) {
    asm("mov.b64 {%0, %1}, %2;" : "=f"(lo), "=f"(hi) : "l"(v));
}
__device__ __forceinline__ u64 shfl_xor64(u64 v, int m) {
    return __shfl_xor_sync(0xffffffffu, v, m);
}

// ---------------- swizzled codebook addressing (128B rows, SW128) ----------
__device__ __forceinline__ const float4* cb_vec(const char* cbb, int k, int j4) {
    return (const float4*)(cbb + k * 128 + ((j4 * 16) ^ ((k & 7) << 4)));
}
__device__ __forceinline__ float cb_el(const char* cbb, int k, int j) {
    return *(const float*)(cbb + k * 128 + ((j * 4) ^ ((k & 7) << 4)));
}

__global__ void __launch_bounds__(THREADS, 1)
lgq_main(const float* __restrict__ z, const float* __restrict__ cbg,
         float* __restrict__ out)
{
    extern __shared__ float sm[];
    char*  cbb  = (char*)sm;
    float* ds   = sm + OFF_DS;
    float* zft  = sm + OFF_ZFT;
    float* zftT = sm + OFF_ZFTT;
    float* red  = sm + OFF_RED;
    int*   idxs = (int*)(sm + OFF_IDX);
    float* scr  = sm + OFF_SCR;

    const int t    = threadIdx.x;
    const int w    = t >> 5;
    const int lane = t & 31;
    const int bx   = blockIdx.x;

    const int c  = bx / BPC;
    const int bi = bx % BPC;
    const int s  = bi * 28 + min(bi, 8);
    const int e  = s + 28 + (bi < 8 ? 1 : 0);

    // ---- stage codebook c (swizzled) ----
    {
        const float4* cb4 = (const float4*)(cbg + (size_t)c * (KK * 32));
        #pragma unroll
        for (int it = 0; it < 16; it++) {
            int idx = t + it * THREADS;
            float4 v = cb4[idx];
            int k = idx >> 3, j4 = idx & 7;
            *(float4*)(cbb + k * 128 + ((j4 * 16) ^ ((k & 7) << 4))) = v;
        }
    }
    float zsq_acc = 0.0f;
    // ---- prestage zf(tile s) ----
    if (t < 256) {
        int jj0 = t >> 3, ni0 = t & 7;
        int n = s * 8 + ni0, b = n >> 10;
        float v = z[(size_t)(b * 256 + c * 32 + jj0) * 1024 + (n & 1023)];
        zft[(s & 1) * 256 + jj0 * 8 + ni0]   = v;
        zftT[(s % 5) * 264 + ni0 * 33 + jj0] = v;
        zsq_acc = v * v;
    }
    __syncthreads();

    // ---- codeword norms for k0 + 256m (p1 warps) ----
    const int k0 = t & 255;
    float cq[4];
    #pragma unroll
    for (int m = 0; m < 4; m++) {
        int k = k0 + 256 * m;
        float sq = 0.0f;
        #pragma unroll
        for (int j4 = 0; j4 < 8; j4++) {
            float4 v = *cb_vec(cbb, k, j4);
            sq += v.x * v.x + v.y * v.y + v.z * v.z + v.w * v.w;
        }
        cq[m] = sq;
    }

    float acc_ne = 0.0f, acc_qd = 0.0f, ct_comm = 0.0f;
    float qbr0 = 0.0f, qbr1 = 0.0f, qbr2 = 0.0f, qbr3 = 0.0f;
    const int t2 = t - 256;    // consumer-group thread id (w >= 8)

    // =====================================================================
    // ONE barrier per iteration. Iter i:
    //   P (w<8):  LDG zf(i+3) | p1(i+2)->ds[i&1] | p2(i+1) (q -> GLOBAL) |
    //             outputs+commitment(i-1) | STS zf(i+3)
    //   C (w>=8): p3(i) from GLOBAL q -> red[i%2] | qbar(i) from GLOBAL q
    // =====================================================================
    for (int i = s - 2; i <= e; i++) {
        if (w < 8) {
            // ---- LDG zf(i+3) ----
            float zn = 0.0f;
            const bool ldg_ok = (i + 3 < e);
            const int jj0 = t >> 3, ni0 = t & 7;
            if (ldg_ok) {
                int n = (i + 3) * 8 + ni0, b = n >> 10;
                zn = z[(size_t)(b * 256 + c * 32 + jj0) * 1024 + (n & 1023)];
            }

            // ---- p1(i+2): dists -> ds[i&1] ----
            if (i + 2 < e) {
                u64 acc[4][4];
                #pragma unroll
                for (int np = 0; np < 4; np++)
                    #pragma unroll
                    for (int m = 0; m < 4; m++) acc[np][m] = 0ull;

                const int sx = (k0 & 7) << 4;
                const float* zb = zft + ((i + 2) & 1) * 256;
                float* dsb = ds + (i & 1) * 8192;   // (i+2)&1 == i&1

                #pragma unroll
                for (int j4 = 0; j4 < 8; j4++) {
                    const int off = (j4 * 16) ^ sx;
                    float4 cv0 = *(const float4*)(cbb + k0 * 128 + off);
                    float4 cv1 = *(const float4*)(cbb + (k0 + 256) * 128 + off);
                    float4 cv2 = *(const float4*)(cbb + (k0 + 512) * 128 + off);
                    float4 cv3 = *(const float4*)(cbb + (k0 + 768) * 128 + off);
                    #pragma unroll
                    for (int eI = 0; eI < 4; eI++) {
                        const ulonglong2* zp =
                            (const ulonglong2*)(zb + (j4 * 4 + eI) * 8);
                        ulonglong2 zA = zp[0], zB = zp[1];
                        float e0 = (eI == 0) ? cv0.x : (eI == 1) ? cv0.y
                                 : (eI == 2) ? cv0.z : cv0.w;
                        float e1 = (eI == 0) ? cv1.x : (eI == 1) ? cv1.y
                                 : (eI == 2) ? cv1.z : cv1.w;
                        float e2 = (eI == 0) ? cv2.x : (eI == 1) ? cv2.y
                                 : (eI == 2) ? cv2.z : cv2.w;
                        float e3 = (eI == 0) ? cv3.x : (eI == 1) ? cv3.y
                                 : (eI == 2) ? cv3.z : cv3.w;
                        u64 d0 = dup2(e0), d1 = dup2(e1);
                        u64 d2 = dup2(e2), d3 = dup2(e3);
                        fma2(acc[0][0], zA.x, d0); fma2(acc[0][1], zA.x, d1);
                        fma2(acc[0][2], zA.x, d2); fma2(acc[0][3], zA.x, d3);
                        fma2(acc[1][0], zA.y, d0); fma2(acc[1][1], zA.y, d1);
                        fma2(acc[1][2], zA.y, d2); fma2(acc[1][3], zA.y, d3);
                        fma2(acc[2][0], zB.x, d0); fma2(acc[2][1], zB.x, d1);
                        fma2(acc[2][2], zB.x, d2); fma2(acc[2][3], zB.x, d3);
                        fma2(acc[3][0], zB.y, d0); fma2(acc[3][1], zB.y, d1);
                        fma2(acc[3][2], zB.y, d2); fma2(acc[3][3], zB.y, d3);
                    }
                }
                #pragma unroll
                for (int np = 0; np < 4; np++)
                    #pragma unroll
                    for (int m = 0; m < 4; m++) {
                        float a, b2; unpk2(acc[np][m], a, b2);
                        int k = k0 + 256 * m;    // canonical layout
                        dsb[(2 * np) * 1024 + k]     = fmaf(-2.0f, a,  cq[m]);
                        dsb[(2 * np + 1) * 1024 + k] = fmaf(-2.0f, b2, cq[m]);
                    }
            }

            // ---- p2(i+1): softmax/argmin row w; q -> GLOBAL only ----
            if (i + 1 >= s && i + 1 < e) {
                const float* row = ds + ((i + 1) & 1) * 8192 + w * 1024;
                const float4* row4 = (const float4*)row;
                float dv[32];
                #pragma unroll
                for (int m4 = 0; m4 < 8; m4++) {
                    float4 v = row4[lane + 32 * m4];
                    dv[m4 * 4 + 0] = v.x; dv[m4 * 4 + 1] = v.y;
                    dv[m4 * 4 + 2] = v.z; dv[m4 * 4 + 3] = v.w;
                }
                float rmin = 3.4e38f; int kmin = 1 << 30;
                #pragma unroll
                for (int ii = 0; ii < 32; ii++) {
                    int k = 4 * lane + 128 * (ii >> 2) + (ii & 3);
                    float dd = dv[ii];
                    if (dd < rmin || (dd == rmin && k < kmin)) { rmin = dd; kmin = k; }
                }
                #pragma unroll
                for (int off = 16; off; off >>= 1) {
                    float od = __shfl_xor_sync(0xffffffffu, rmin, off);
                    int   ok = __shfl_xor_sync(0xffffffffu, kmin, off);
                    if (od < rmin || (od == rmin && ok < kmin)) { rmin = od; kmin = ok; }
                }
                float Z = 0.0f, sed = 0.0f;
                #pragma unroll
                for (int ii = 0; ii < 32; ii++) {
                    float told = dv[ii];
                    float ev = __expf((rmin - told) * 0.5f);
                    Z += ev;
                    sed = fmaf(ev, told, sed);
                    dv[ii] = ev;
                }
                #pragma unroll
                for (int off = 16; off; off >>= 1) {
                    Z   += __shfl_xor_sync(0xffffffffu, Z, off);
                    sed += __shfl_xor_sync(0xffffffffu, sed, off);
                }
                float rZ = __fdividef(1.0f, Z);
                float qd = sed * rZ;

                int n = (i + 1) * 8 + w;
                float4* gq4 = (float4*)(out + O_Q + ((size_t)n * 8 + c) * 1024);
                #pragma unroll
                for (int m4 = 0; m4 < 8; m4++) {
                    float4 qv;
                    qv.x = dv[m4 * 4 + 0] * rZ; qv.y = dv[m4 * 4 + 1] * rZ;
                    qv.z = dv[m4 * 4 + 2] * rZ; qv.w = dv[m4 * 4 + 3] * rZ;
                    gq4[lane + 32 * m4] = qv;
                }
                if (lane == 0) {
                    acc_ne += 0.5f * (rmin - qd) - __logf(Z);
                    acc_qd += qd;
                    idxs[((i + 1) % 3) * 8 + w] = kmin;
                }
            }

            // ---- outputs + commitment for tile (i-1) ----
            if (i >= s + 1) {
                const int ti = i - 1;
                {
                    int ni0 = t & 7, jq = t >> 3;
                    int n = ti * 8 + ni0, b = n >> 10;
                    int kq = idxs[(ti % 3) * 8 + ni0];
                    out[(size_t)(b * 256 + c * 32 + jq) * 1024 + (n & 1023)] =
                        cb_el(cbb, kq, jq);
                }
                if (t < 8) {
                    int n = ti * 8 + t, b = n >> 10;
                    out[O_IDX + (size_t)b * 8192 + c * 1024 + (n & 1023)] =
                        (float)idxs[(ti % 3) * 8 + t];
                }
                {
                    int cn = t >> 5, cj = t & 31;
                    const float* rd = red + (ti & 1) * 2048;
                    float sr = 0.0f;
                    #pragma unroll
                    for (int ss = 0; ss < 8; ss++)
                        sr += rd[ss * 256 + cn * 32 + cj];
                    float diff = zftT[(ti % 5) * 264 + cn * 33 + cj] - sr;
                    ct_comm = fmaf(diff, diff, ct_comm);
                }
            }

            // ---- STS zf(i+3) ----
            if (ldg_ok) {
                zft[((i + 3) & 1) * 256 + jj0 * 8 + ni0]   = zn;
                zftT[((i + 3) % 5) * 264 + ni0 * 33 + jj0] = zn;
                zsq_acc += zn * zn;
            }
        } else {
            // ================= C: p3(i) + qbar(i) from GLOBAL q ===========
            if (i >= s && i < e) {
                const int s3 = w - 8;
                const int ks = lane >> 3;
                const int jg = lane & 7;
                const float* gq = out + O_Q + (size_t)c * 1024
                                + (size_t)i * 8 * 8192;
                u64 acc[8][2];
                #pragma unroll
                for (int n2 = 0; n2 < 8; n2++) { acc[n2][0] = 0ull; acc[n2][1] = 0ull; }

                #pragma unroll
                for (int i4 = 0; i4 < 8; i4++) {
                    const int kb = s3 * 128 + ks * 32 + i4 * 4;
                    u64 cj0[4], cj1[4];
                    #pragma unroll
                    for (int eI = 0; eI < 4; eI++) {
                        const float4 v = *(const float4*)(cbb + (kb + eI) * 128 +
                            ((jg * 16) ^ (((kb + eI) & 7) << 4)));
                        cj0[eI] = pk2(v.x, v.y);
                        cj1[eI] = pk2(v.z, v.w);
                    }
                    #pragma unroll
                    for (int n2 = 0; n2 < 8; n2++) {
                        const float4 qv =
                            *(const float4*)(gq + (size_t)n2 * 8192 + kb);
                        u64 dx = dup2(qv.x), dy = dup2(qv.y);
                        u64 dz = dup2(qv.z), dw = dup2(qv.w);
                        fma2(acc[n2][0], dx, cj0[0]); fma2(acc[n2][1], dx, cj1[0]);
                        fma2(acc[n2][0], dy, cj0[1]); fma2(acc[n2][1], dy, cj1[1]);
                        fma2(acc[n2][0], dz, cj0[2]); fma2(acc[n2][1], dz, cj1[2]);
                        fma2(acc[n2][0], dw, cj0[3]); fma2(acc[n2][1], dw, cj1[3]);
                    }
                }
                #pragma unroll
                for (int n2 = 0; n2 < 8; n2++) {
                    acc[n2][0] = add2(acc[n2][0], shfl_xor64(acc[n2][0], 8));
                    acc[n2][1] = add2(acc[n2][1], shfl_xor64(acc[n2][1], 8));
                    acc[n2][0] = add2(acc[n2][0], shfl_xor64(acc[n2][0], 16));
                    acc[n2][1] = add2(acc[n2][1], shfl_xor64(acc[n2][1], 16));
                }
                u64 r0a = acc[0][0], r1a = acc[0][1];
                u64 r0b = acc[1][0], r1b = acc[1][1];
                if (ks == 1) { r0a = acc[2][0]; r1a = acc[2][1];
                               r0b = acc[3][0]; r1b = acc[3][1]; }
                if (ks == 2) { r0a = acc[4][0]; r1a = acc[4][1];
                               r0b = acc[5][0]; r1b = acc[5][1]; }
                if (ks == 3) { r0a = acc[6][0]; r1a = acc[6][1];
                               r0b = acc[7][0]; r1b = acc[7][1]; }
                float a0, a1, a2, a3;
                float* rd = red + (i & 1) * 2048;
                unpk2(r0a, a0, a1); unpk2(r1a, a2, a3);
                *(float4*)(rd + s3 * 256 + (ks * 2) * 32 + jg * 4) =
                    make_float4(a0, a1, a2, a3);
                unpk2(r0b, a0, a1); unpk2(r1b, a2, a3);
                *(float4*)(rd + s3 * 256 + (ks * 2 + 1) * 32 + jg * 4) =
                    make_float4(a0, a1, a2, a3);

                // qbar from global q (coalesced across t2)
                float s0 = 0.0f, s1 = 0.0f, s2 = 0.0f, s3p = 0.0f;
                #pragma unroll
                for (int n2 = 0; n2 < 8; n2++) {
                    const float* qr = gq + (size_t)n2 * 8192;
                    s0  += qr[t2];
                    s1  += qr[t2 + 256];
                    s2  += qr[t2 + 512];
                    s3p += qr[t2 + 768];
                }
                qbr0 += s0; qbr1 += s1; qbr2 += s2; qbr3 += s3p;
            }
        }
        __syncthreads();
    }

    // ---- flush accumulators ----
    #pragma unroll
    for (int off = 16; off; off >>= 1) {
        ct_comm += __shfl_xor_sync(0xffffffffu, ct_comm, off);
        zsq_acc += __shfl_xor_sync(0xffffffffu, zsq_acc, off);
    }
    if (lane == 0) {
        atomicAdd(&g_comm, ct_comm);
        atomicAdd(&g_qd, zsq_acc + ((w < 8) ? acc_qd : 0.0f));
        if (w < 8) atomicAdd(&g_ne, acc_ne);
    }
    if (w >= 8) {
        atomicAdd(&g_qbar[c * 1024 + t2],       qbr0);
        atomicAdd(&g_qbar[c * 1024 + t2 + 256], qbr1);
        atomicAdd(&g_qbar[c * 1024 + t2 + 512], qbr2);
        atomicAdd(&g_qbar[c * 1024 + t2 + 768], qbr3);
    }

    // ---- last-block finalize (ticket) ----
    __threadfence();
    int* flag = (int*)(sm + OFF_FLG);
    if (t == 0) {
        unsigned int v = atomicAdd(&g_count, 1u);
        flag[0] = (v == (unsigned)(NBLOCKS - 1));
    }
    __syncthreads();
    if (flag[0]) {
        float local = 0.0f;
        #pragma unroll
        for (int it = 0; it < 16; it++) {
            int idx = t + it * THREADS;
            float qb = g_qbar[idx] * (1.0f / 4096.0f);
            local += qb * __logf(fmaf(qb, 1024.0f, 1e-8f));
            g_qbar[idx] = 0.0f;                 // reset for next graph replay
        }
        #pragma unroll
        for (int off = 16; off; off >>= 1)
            local += __shfl_xor_sync(0xffffffffu, local, off);
        if (lane == 0) scr[w] = local;
        __syncthreads();
        if (t == 0) {
            float sr = 0.0f;
            #pragma unroll
            for (int ii = 0; ii < 16; ii++) sr += scr[ii];
            float balance = sr * 0.125f;
            float comm = g_comm * (1.0f / 1048576.0f);
            float mne  = g_ne   * (1.0f / 32768.0f);
            float mqd  = g_qd   * (1.0f / 32768.0f);
            out[O_SC + 0] = comm;
            out[O_SC + 1] = fmaf(mqd, 0.5f, mne) + 6.93147180559945f;
            out[O_SC + 2] = -mne;
            out[O_SC + 3] = balance;
            out[O_SC + 4] = 1.0f;
            g_comm = 0.0f; g_ne = 0.0f; g_qd = 0.0f;
            g_count = 0u;
        }
    }
}

extern "C" void kernel_launch(void* const* d_in, const int* in_sizes, int n_in,
                              void* d_out, int out_size)
{
    const float* z   = (const float*)d_in[0];   // (4,256,32,32) f32
    const float* cbg = (const float*)d_in[1];   // (8,1024,32)  f32
    float* out = (float*)d_out;

    cudaFuncSetAttribute(lgq_main, cudaFuncAttributeMaxDynamicSharedMemorySize,
                         SMEM_BYTES);
    lgq_main<<<NBLOCKS, THREADS, SMEM_BYTES>>>(z, cbg, out);
}